// round 10
// baseline (speedup 1.0000x reference)
#include <cuda_runtime.h>
#include <cstdint>

// Problem shape (fixed by reference)
#define T_DIM 16384
#define B_DIM 64
#define E_DIM 4096

#define TILE_ROWS 16
#define NTILES    (T_DIM / TILE_ROWS)   // 1024

// ---------------------------------------------------------------------------
// Decoupled-lookback state (allocation-free __device__ globals).
// flag: 0 = nothing, 1 = aggregate published, 2 = inclusive prefix published.
// Payloads packed into 8B for single-instruction volatile ld/st (no tearing).
// ---------------------------------------------------------------------------
__device__ int g_tile_counter;
__device__ volatile int g_flag[NTILES];
__device__ volatile unsigned long long g_agg[NTILES];
__device__ volatile unsigned long long g_pref[NTILES];

__device__ __forceinline__ unsigned long long pack2(float a, float b) {
    return ((unsigned long long)__float_as_uint(b) << 32) | (unsigned long long)__float_as_uint(a);
}
__device__ __forceinline__ float2 unpack2(unsigned long long v) {
    return make_float2(__uint_as_float((unsigned)v), __uint_as_float((unsigned)(v >> 32)));
}

// Reset lookback state before every fused launch (graph-replay safe).
__global__ void init_kernel() {
    int i = blockIdx.x * blockDim.x + threadIdx.x;
    if (i < NTILES) g_flag[i] = 0;
    if (i == 0) g_tile_counter = 0;
}

// ---------------------------------------------------------------------------
// Single-pass fused kernel: gather+reduce -> chained scan -> broadcast store.
// One block = one tile of 16 t-rows. Gather latency (L1tex replay bound,
// ~10us standalone) overlaps with the DRAM-write stream of other tiles.
// Compose (ordered): compose(earlier=(A,B), later=(a,b)) = (a*A, a*B + b)
// ---------------------------------------------------------------------------
__global__ void __launch_bounds__(256) fused_kernel(
        const int* __restrict__ indices, const float* __restrict__ params,
        const float* __restrict__ M_prev, float* __restrict__ out) {
    __shared__ float2 s_ab[TILE_ROWS];     // per-row (alpha, beta)
    __shared__ float2 s_rowAB[TILE_ROWS];  // per-row scanned (A, B)
    __shared__ float2 s_excl;
    __shared__ int s_tile;

    const int tid  = threadIdx.x;
    const int lane = tid & 31;
    const int wid  = tid >> 5;

    // Dynamic tile assignment: guarantees resident blocks own the lowest
    // unfinished tiles -> lookback cannot deadlock.
    if (tid == 0) s_tile = atomicAdd(&g_tile_counter, 1);

    // Load M_prev chunk while the atomic is in flight (independent work).
    const float4* M4 = (const float4*)M_prev;                  // E/4 = 1024
    float4 m0 = __ldg(&M4[tid]);
    float4 m1 = __ldg(&M4[256 + tid]);
    float4 m2 = __ldg(&M4[512 + tid]);
    float4 m3 = __ldg(&M4[768 + tid]);

    __syncthreads();
    const int tile = s_tile;
    const int t0   = tile * TILE_ROWS;

    // ---- Phase A: gather + reduce 16 rows (warp w -> rows 2w, 2w+1) ------
    {
        const float2* p2 = (const float2*)params;
        const int r0 = wid * 2;
        int2 i0 = ((const int2*)(indices + (size_t)(t0 + r0)     * B_DIM))[lane];
        int2 i1 = ((const int2*)(indices + (size_t)(t0 + r0 + 1) * B_DIM))[lane];
        float2 a0 = __ldg(&p2[i0.x]);
        float2 b0 = __ldg(&p2[i0.y]);
        float2 a1 = __ldg(&p2[i1.x]);
        float2 b1 = __ldg(&p2[i1.y]);
        float s0a = a0.x + b0.x, s0b = a0.y + b0.y;
        float s1a = a1.x + b1.x, s1b = a1.y + b1.y;
        #pragma unroll
        for (int off = 16; off > 0; off >>= 1) {
            s0a += __shfl_xor_sync(0xFFFFFFFFu, s0a, off);
            s0b += __shfl_xor_sync(0xFFFFFFFFu, s0b, off);
            s1a += __shfl_xor_sync(0xFFFFFFFFu, s1a, off);
            s1b += __shfl_xor_sync(0xFFFFFFFFu, s1b, off);
        }
        if (lane == 0) {
            s_ab[r0]     = make_float2(s0a, s0b);
            s_ab[r0 + 1] = make_float2(s1a, s1b);
        }
    }
    __syncthreads();

    // ---- Phase B: 16-lane scan + decoupled lookback (warp 0) -------------
    if (wid == 0) {
        float wa = 1.0f, wb = 0.0f;
        if (lane < TILE_ROWS) { wa = s_ab[lane].x; wb = s_ab[lane].y; }
        // inclusive scan over 16 lanes: new = compose(lower, mine)
        #pragma unroll
        for (int off = 1; off < TILE_ROWS; off <<= 1) {
            float pa = __shfl_up_sync(0xFFFFFFFFu, wa, off);
            float pb = __shfl_up_sync(0xFFFFFFFFu, wb, off);
            float na = (lane >= off) ? wa * pa        : wa;
            float nb = (lane >= off) ? fmaf(wa, pb, wb) : wb;
            wa = na; wb = nb;
        }
        float aga = __shfl_sync(0xFFFFFFFFu, wa, TILE_ROWS - 1);
        float agb = __shfl_sync(0xFFFFFFFFu, wb, TILE_ROWS - 1);

        if (lane == 0) {
            // publish aggregate
            g_agg[tile] = pack2(aga, agb);
            __threadfence();
            g_flag[tile] = 1;

            // lookback: accumulate segments (j..tile-1), earliest-first compose
            float ea = 1.0f, eb = 0.0f;
            if (tile > 0) {
                float acc_a = 1.0f, acc_b = 0.0f;
                int j = tile - 1;
                bool done = false;
                while (j >= 0) {
                    int f;
                    while ((f = g_flag[j]) == 0) { }   // spin
                    __threadfence();
                    if (f == 2) {
                        float2 p = unpack2(g_pref[j]);
                        ea = acc_a * p.x;
                        eb = fmaf(acc_a, p.y, acc_b);
                        done = true;
                        break;
                    } else {
                        float2 g = unpack2(g_agg[j]);
                        float na = acc_a * g.x;
                        float nb = fmaf(acc_a, g.y, acc_b);
                        acc_a = na; acc_b = nb;
                        j--;
                    }
                }
                if (!done) { ea = acc_a; eb = acc_b; }  // consumed all aggregates
            }
            // publish inclusive prefix = compose(excl, aggregate)
            g_pref[tile] = pack2(aga * ea, fmaf(aga, eb, agb));
            __threadfence();
            g_flag[tile] = 2;
            s_excl = make_float2(ea, eb);
        }
        __syncwarp();
        float2 ex = s_excl;
        if (lane < TILE_ROWS) {
            // per-row scanned value = compose(excl, local_inclusive)
            s_rowAB[lane] = make_float2(wa * ex.x, fmaf(wa, ex.y, wb));
        }
    }
    __syncthreads();

    // ---- Phase C: broadcast store, 16 rows x 4096 (64 STG.128/thread) ----
    float4* o4 = (float4*)out + (size_t)t0 * (E_DIM / 4);
    #pragma unroll
    for (int r = 0; r < TILE_ROWS; r++) {
        float a = s_rowAB[r].x;
        float b = s_rowAB[r].y;
        float4 v0, v1, v2, v3;
        v0.x = fmaf(a, m0.x, b); v0.y = fmaf(a, m0.y, b); v0.z = fmaf(a, m0.z, b); v0.w = fmaf(a, m0.w, b);
        v1.x = fmaf(a, m1.x, b); v1.y = fmaf(a, m1.y, b); v1.z = fmaf(a, m1.z, b); v1.w = fmaf(a, m1.w, b);
        v2.x = fmaf(a, m2.x, b); v2.y = fmaf(a, m2.y, b); v2.z = fmaf(a, m2.z, b); v2.w = fmaf(a, m2.w, b);
        v3.x = fmaf(a, m3.x, b); v3.y = fmaf(a, m3.y, b); v3.z = fmaf(a, m3.z, b); v3.w = fmaf(a, m3.w, b);
        float4* row = o4 + (size_t)r * (E_DIM / 4);
        __stcs(row + tid,       v0);
        __stcs(row + 256 + tid, v1);
        __stcs(row + 512 + tid, v2);
        __stcs(row + 768 + tid, v3);
    }
}

// ---------------------------------------------------------------------------
extern "C" void kernel_launch(void* const* d_in, const int* in_sizes, int n_in,
                              void* d_out, int out_size) {
    const int*   indices = (const int*)d_in[0];   // (T, B) int32 (JAX downcast)
    const float* M_prev  = (const float*)d_in[1]; // (E,)   f32
    const float* params  = (const float*)d_in[2]; // (N, 2) f32
    float*       out     = (float*)d_out;         // (T, E) f32

    init_kernel<<<1, 1024>>>();
    fused_kernel<<<NTILES, 256>>>(indices, params, M_prev, out);
}

// round 11
// speedup vs baseline: 1.5439x; 1.5439x over previous
#include <cuda_runtime.h>
#include <cstdint>

// Problem shape (fixed by reference)
#define T_DIM 16384
#define B_DIM 64
#define E_DIM 4096

#define TILE_ROWS 16
#define NTILES    (T_DIM / TILE_ROWS)   // 1024

// ---------------------------------------------------------------------------
// Decoupled-lookback state (allocation-free __device__ globals).
// flag: 0 = nothing, 1 = aggregate published, 2 = inclusive prefix published.
// Payloads packed into 8B for single-instruction volatile ld/st (no tearing).
// ---------------------------------------------------------------------------
__device__ int g_tile_counter;
__device__ volatile int g_flag[NTILES];
__device__ volatile unsigned long long g_agg[NTILES];
__device__ volatile unsigned long long g_pref[NTILES];

__device__ __forceinline__ unsigned long long pack2(float a, float b) {
    return ((unsigned long long)__float_as_uint(b) << 32) | (unsigned long long)__float_as_uint(a);
}
__device__ __forceinline__ float2 unpack2(unsigned long long v) {
    return make_float2(__uint_as_float((unsigned)v), __uint_as_float((unsigned)(v >> 32)));
}

// Reset lookback state before every fused launch (graph-replay safe).
__global__ void init_kernel() {
    int i = blockIdx.x * blockDim.x + threadIdx.x;
    if (i < NTILES) g_flag[i] = 0;
    if (i == 0) g_tile_counter = 0;
}

// ---------------------------------------------------------------------------
// Single-pass fused kernel: gather+reduce -> chained scan (warp-parallel
// decoupled lookback) -> broadcast store.
// Compose (ordered): compose(earlier=(A,B), later=(a,b)) = (a*A, a*B + b)
// ---------------------------------------------------------------------------
__global__ void __launch_bounds__(256) fused_kernel(
        const int* __restrict__ indices, const float* __restrict__ params,
        const float* __restrict__ M_prev, float* __restrict__ out) {
    __shared__ float2 s_ab[TILE_ROWS];     // per-row (alpha, beta)
    __shared__ float2 s_rowAB[TILE_ROWS];  // per-row scanned (A, B)
    __shared__ int s_tile;

    const int tid  = threadIdx.x;
    const int lane = tid & 31;
    const int wid  = tid >> 5;

    // Dynamic tile assignment: resident blocks own the lowest unfinished
    // tiles -> lookback cannot deadlock.
    if (tid == 0) s_tile = atomicAdd(&g_tile_counter, 1);

    // Load M_prev chunk while the atomic is in flight.
    const float4* M4 = (const float4*)M_prev;                  // E/4 = 1024
    float4 m0 = __ldg(&M4[tid]);
    float4 m1 = __ldg(&M4[256 + tid]);
    float4 m2 = __ldg(&M4[512 + tid]);
    float4 m3 = __ldg(&M4[768 + tid]);

    __syncthreads();
    const int tile = s_tile;
    const int t0   = tile * TILE_ROWS;

    // ---- Phase A: gather + reduce 16 rows (warp w -> rows 2w, 2w+1) ------
    {
        const float2* p2 = (const float2*)params;
        const int r0 = wid * 2;
        int2 i0 = ((const int2*)(indices + (size_t)(t0 + r0)     * B_DIM))[lane];
        int2 i1 = ((const int2*)(indices + (size_t)(t0 + r0 + 1) * B_DIM))[lane];
        float2 a0 = __ldg(&p2[i0.x]);
        float2 b0 = __ldg(&p2[i0.y]);
        float2 a1 = __ldg(&p2[i1.x]);
        float2 b1 = __ldg(&p2[i1.y]);
        float s0a = a0.x + b0.x, s0b = a0.y + b0.y;
        float s1a = a1.x + b1.x, s1b = a1.y + b1.y;
        #pragma unroll
        for (int off = 16; off > 0; off >>= 1) {
            s0a += __shfl_xor_sync(0xFFFFFFFFu, s0a, off);
            s0b += __shfl_xor_sync(0xFFFFFFFFu, s0b, off);
            s1a += __shfl_xor_sync(0xFFFFFFFFu, s1a, off);
            s1b += __shfl_xor_sync(0xFFFFFFFFu, s1b, off);
        }
        if (lane == 0) {
            s_ab[r0]     = make_float2(s0a, s0b);
            s_ab[r0 + 1] = make_float2(s1a, s1b);
        }
    }
    __syncthreads();

    // ---- Phase B: 16-lane tile scan + WARP-PARALLEL lookback (warp 0) ----
    if (wid == 0) {
        // inclusive ordered scan over the 16 row (alpha,beta) pairs
        float wa = 1.0f, wb = 0.0f;
        if (lane < TILE_ROWS) { wa = s_ab[lane].x; wb = s_ab[lane].y; }
        #pragma unroll
        for (int off = 1; off < TILE_ROWS; off <<= 1) {
            float pa = __shfl_up_sync(0xFFFFFFFFu, wa, off);
            float pb = __shfl_up_sync(0xFFFFFFFFu, wb, off);
            float na = (lane >= off) ? wa * pa        : wa;
            float nb = (lane >= off) ? fmaf(wa, pb, wb) : wb;
            wa = na; wb = nb;
        }
        float aga = __shfl_sync(0xFFFFFFFFu, wa, TILE_ROWS - 1);
        float agb = __shfl_sync(0xFFFFFFFFu, wb, TILE_ROWS - 1);

        // publish aggregate ASAP
        if (lane == 0) {
            g_agg[tile] = pack2(aga, agb);
            __threadfence();
            g_flag[tile] = 1;
        }

        // warp-parallel lookback: 32 predecessors per window step
        float ea = 1.0f, eb = 0.0f;      // exclusive prefix (result)
        if (tile > 0) {
            float acc_a = 1.0f, acc_b = 0.0f;  // combo of consumed later segments
            int base_hi = tile - 1;
            for (;;) {
                int j = base_hi - 31 + lane;       // lane ascending == j ascending
                bool valid = (j >= 0);
                int f = 0;
                if (valid) {
                    do { f = g_flag[j]; } while (f == 0);
                }
                __threadfence();
                unsigned mask2 = __ballot_sync(0xFFFFFFFFu, valid && (f == 2));
                int lead = mask2 ? (31 - __clz(mask2)) : -1;  // highest lane w/ prefix

                // per-lane window value (identity below the prefix lane)
                float va = 1.0f, vb = 0.0f;
                if (valid && lane >= lead) {
                    unsigned long long payload = (lane == lead) ? g_pref[j] : g_agg[j];
                    float2 p = unpack2(payload);
                    va = p.x; vb = p.y;
                }
                // ordered inclusive scan; lane 31 ends with the window combo
                #pragma unroll
                for (int off = 1; off < 32; off <<= 1) {
                    float pa = __shfl_up_sync(0xFFFFFFFFu, va, off);
                    float pb = __shfl_up_sync(0xFFFFFFFFu, vb, off);
                    float na = (lane >= off) ? va * pa        : va;
                    float nb = (lane >= off) ? fmaf(va, pb, vb) : vb;
                    va = na; vb = nb;
                }
                float cwa = __shfl_sync(0xFFFFFFFFu, va, 31);
                float cwb = __shfl_sync(0xFFFFFFFFu, vb, 31);

                if (lead >= 0) {
                    // window combo already includes a full prefix -> done
                    ea = acc_a * cwa;
                    eb = fmaf(acc_a, cwb, acc_b);
                    break;
                }
                // consume window of aggregates, move back
                float na = acc_a * cwa;
                float nb = fmaf(acc_a, cwb, acc_b);
                acc_a = na; acc_b = nb;
                base_hi -= 32;
                if (base_hi < 0) {  // consumed everything back to tile 0
                    ea = acc_a; eb = acc_b;
                    break;
                }
            }
        }

        // publish inclusive prefix = compose(excl, aggregate)
        if (lane == 0) {
            g_pref[tile] = pack2(aga * ea, fmaf(aga, eb, agb));
            __threadfence();
            g_flag[tile] = 2;
        }

        // per-row scanned value = compose(excl, local_inclusive)
        if (lane < TILE_ROWS) {
            s_rowAB[lane] = make_float2(wa * ea, fmaf(wa, eb, wb));
        }
    }
    __syncthreads();

    // ---- Phase C: broadcast store, 16 rows x 4096 (64 STG.128/thread) ----
    float4* o4 = (float4*)out + (size_t)t0 * (E_DIM / 4);
    #pragma unroll
    for (int r = 0; r < TILE_ROWS; r++) {
        float a = s_rowAB[r].x;
        float b = s_rowAB[r].y;
        float4 v0, v1, v2, v3;
        v0.x = fmaf(a, m0.x, b); v0.y = fmaf(a, m0.y, b); v0.z = fmaf(a, m0.z, b); v0.w = fmaf(a, m0.w, b);
        v1.x = fmaf(a, m1.x, b); v1.y = fmaf(a, m1.y, b); v1.z = fmaf(a, m1.z, b); v1.w = fmaf(a, m1.w, b);
        v2.x = fmaf(a, m2.x, b); v2.y = fmaf(a, m2.y, b); v2.z = fmaf(a, m2.z, b); v2.w = fmaf(a, m2.w, b);
        v3.x = fmaf(a, m3.x, b); v3.y = fmaf(a, m3.y, b); v3.z = fmaf(a, m3.z, b); v3.w = fmaf(a, m3.w, b);
        float4* row = o4 + (size_t)r * (E_DIM / 4);
        __stcs(row + tid,       v0);
        __stcs(row + 256 + tid, v1);
        __stcs(row + 512 + tid, v2);
        __stcs(row + 768 + tid, v3);
    }
}

// ---------------------------------------------------------------------------
extern "C" void kernel_launch(void* const* d_in, const int* in_sizes, int n_in,
                              void* d_out, int out_size) {
    const int*   indices = (const int*)d_in[0];   // (T, B) int32 (JAX downcast)
    const float* M_prev  = (const float*)d_in[1]; // (E,)   f32
    const float* params  = (const float*)d_in[2]; // (N, 2) f32
    float*       out     = (float*)d_out;         // (T, E) f32

    init_kernel<<<1, 1024>>>();
    fused_kernel<<<NTILES, 256>>>(indices, params, M_prev, out);
}

// round 12
// speedup vs baseline: 1.7600x; 1.1399x over previous
#include <cuda_runtime.h>
#include <cstdint>

// Problem shape (fixed by reference)
#define T_DIM 16384
#define B_DIM 64
#define E_DIM 4096

#define TILE_ROWS 32
#define NTILES    (T_DIM / TILE_ROWS)   // 512
#define THREADS   512

// ---------------------------------------------------------------------------
// Decoupled-lookback state. NEVER reset: flags are epoch-encoded.
// For epoch e (= replay count): flag 2e+1 = aggregate published,
// flag 2e+2 = inclusive prefix published. Stale flags (<= 2e) read as
// "not ready", so no init kernel is needed and replays stay deterministic.
// ---------------------------------------------------------------------------
__device__ int g_ticket;                              // monotone across replays
__device__ volatile int g_flag[NTILES];               // zero-init
__device__ volatile unsigned long long g_agg[NTILES];
__device__ volatile unsigned long long g_pref[NTILES];

__device__ __forceinline__ unsigned long long pack2(float a, float b) {
    return ((unsigned long long)__float_as_uint(b) << 32) | (unsigned long long)__float_as_uint(a);
}
__device__ __forceinline__ float2 unpack2(unsigned long long v) {
    return make_float2(__uint_as_float((unsigned)v), __uint_as_float((unsigned)(v >> 32)));
}

// ---------------------------------------------------------------------------
// Single-pass fused kernel: gather+reduce -> chained scan (warp-parallel
// decoupled lookback, epoch flags) -> broadcast store.
// Compose (ordered): compose(earlier=(A,B), later=(a,b)) = (a*A, a*B + b)
// ---------------------------------------------------------------------------
__global__ void __launch_bounds__(THREADS) fused_kernel(
        const int* __restrict__ indices, const float* __restrict__ params,
        const float* __restrict__ M_prev, float* __restrict__ out) {
    __shared__ float2 s_ab[TILE_ROWS];     // per-row (alpha, beta)
    __shared__ float2 s_rowAB[TILE_ROWS];  // per-row scanned (A, B)
    __shared__ int s_ticket;

    const int tid  = threadIdx.x;
    const int lane = tid & 31;
    const int wid  = tid >> 5;

    // Dynamic tile assignment: resident blocks own the lowest unfinished
    // tiles -> lookback cannot deadlock. Ticket is monotone across replays.
    if (tid == 0) s_ticket = atomicAdd(&g_ticket, 1);

    // Load M_prev chunk while the atomic is in flight. E/4 = 1024 float4.
    const float4* M4 = (const float4*)M_prev;
    float4 m0 = __ldg(&M4[tid]);
    float4 m1 = __ldg(&M4[THREADS + tid]);

    __syncthreads();
    const int ticket = s_ticket;
    const int tile   = ticket & (NTILES - 1);
    const int agg_lo = ((ticket >> 9) << 1) + 1;   // 2*epoch + 1
    const int t0     = tile * TILE_ROWS;

    // ---- Phase A: gather + reduce 32 rows (warp w -> rows 2w, 2w+1) ------
    {
        const float2* p2 = (const float2*)params;
        const int r0 = wid * 2;
        int2 i0 = ((const int2*)(indices + (size_t)(t0 + r0)     * B_DIM))[lane];
        int2 i1 = ((const int2*)(indices + (size_t)(t0 + r0 + 1) * B_DIM))[lane];
        float2 a0 = __ldg(&p2[i0.x]);
        float2 b0 = __ldg(&p2[i0.y]);
        float2 a1 = __ldg(&p2[i1.x]);
        float2 b1 = __ldg(&p2[i1.y]);
        float s0a = a0.x + b0.x, s0b = a0.y + b0.y;
        float s1a = a1.x + b1.x, s1b = a1.y + b1.y;
        #pragma unroll
        for (int off = 16; off > 0; off >>= 1) {
            s0a += __shfl_xor_sync(0xFFFFFFFFu, s0a, off);
            s0b += __shfl_xor_sync(0xFFFFFFFFu, s0b, off);
            s1a += __shfl_xor_sync(0xFFFFFFFFu, s1a, off);
            s1b += __shfl_xor_sync(0xFFFFFFFFu, s1b, off);
        }
        if (lane == 0) {
            s_ab[r0]     = make_float2(s0a, s0b);
            s_ab[r0 + 1] = make_float2(s1a, s1b);
        }
    }
    __syncthreads();

    // ---- Phase B: 32-lane tile scan + warp-parallel lookback (warp 0) ----
    if (wid == 0) {
        // inclusive ordered scan over the 32 row (alpha,beta) pairs
        float wa = s_ab[lane].x, wb = s_ab[lane].y;
        #pragma unroll
        for (int off = 1; off < 32; off <<= 1) {
            float pa = __shfl_up_sync(0xFFFFFFFFu, wa, off);
            float pb = __shfl_up_sync(0xFFFFFFFFu, wb, off);
            float na = (lane >= off) ? wa * pa          : wa;
            float nb = (lane >= off) ? fmaf(wa, pb, wb) : wb;
            wa = na; wb = nb;
        }
        float aga = __shfl_sync(0xFFFFFFFFu, wa, 31);
        float agb = __shfl_sync(0xFFFFFFFFu, wb, 31);

        // publish aggregate ASAP
        if (lane == 0) {
            g_agg[tile] = pack2(aga, agb);
            __threadfence();
            g_flag[tile] = agg_lo;
        }

        // warp-parallel lookback: 32 predecessors per window step
        float ea = 1.0f, eb = 0.0f;            // exclusive prefix (result)
        if (tile > 0) {
            float acc_a = 1.0f, acc_b = 0.0f;  // combo of consumed later segments
            int base_hi = tile - 1;
            for (;;) {
                int j = base_hi - 31 + lane;   // lane ascending == j ascending
                bool valid = (j >= 0);
                int f = 0;
                if (valid) {
                    f = g_flag[j];
                    while (f < agg_lo) { __nanosleep(40); f = g_flag[j]; }
                }
                __threadfence();
                unsigned mask2 = __ballot_sync(0xFFFFFFFFu, valid && (f > agg_lo));
                int lead = mask2 ? (31 - __clz(mask2)) : -1;  // highest lane w/ prefix

                // per-lane window value (identity below the prefix lane)
                float va = 1.0f, vb = 0.0f;
                if (valid && lane >= lead) {
                    unsigned long long payload = (lane == lead) ? g_pref[j] : g_agg[j];
                    float2 p = unpack2(payload);
                    va = p.x; vb = p.y;
                }
                // ordered inclusive scan; lane 31 ends with the window combo
                #pragma unroll
                for (int off = 1; off < 32; off <<= 1) {
                    float pa = __shfl_up_sync(0xFFFFFFFFu, va, off);
                    float pb = __shfl_up_sync(0xFFFFFFFFu, vb, off);
                    float na = (lane >= off) ? va * pa          : va;
                    float nb = (lane >= off) ? fmaf(va, pb, vb) : vb;
                    va = na; vb = nb;
                }
                float cwa = __shfl_sync(0xFFFFFFFFu, va, 31);
                float cwb = __shfl_sync(0xFFFFFFFFu, vb, 31);

                if (lead >= 0) {
                    ea = acc_a * cwa;
                    eb = fmaf(acc_a, cwb, acc_b);
                    break;
                }
                float na = acc_a * cwa;
                float nb = fmaf(acc_a, cwb, acc_b);
                acc_a = na; acc_b = nb;
                base_hi -= 32;
                if (base_hi < 0) {   // consumed everything back to tile 0
                    ea = acc_a; eb = acc_b;
                    break;
                }
            }
        }

        // publish inclusive prefix = compose(excl, aggregate)
        if (lane == 0) {
            g_pref[tile] = pack2(aga * ea, fmaf(aga, eb, agb));
            __threadfence();
            g_flag[tile] = agg_lo + 1;
        }

        // per-row scanned value = compose(excl, local_inclusive)
        s_rowAB[lane] = make_float2(wa * ea, fmaf(wa, eb, wb));
    }
    __syncthreads();

    // ---- Phase C: broadcast store, 32 rows x 4096 (64 STG.128/thread) ----
    float4* o4 = (float4*)out + (size_t)t0 * (E_DIM / 4);
    #pragma unroll
    for (int r = 0; r < TILE_ROWS; r++) {
        float a = s_rowAB[r].x;
        float b = s_rowAB[r].y;
        float4 v0, v1;
        v0.x = fmaf(a, m0.x, b); v0.y = fmaf(a, m0.y, b);
        v0.z = fmaf(a, m0.z, b); v0.w = fmaf(a, m0.w, b);
        v1.x = fmaf(a, m1.x, b); v1.y = fmaf(a, m1.y, b);
        v1.z = fmaf(a, m1.z, b); v1.w = fmaf(a, m1.w, b);
        float4* row = o4 + (size_t)r * (E_DIM / 4);
        __stcs(row + tid,           v0);
        __stcs(row + THREADS + tid, v1);
    }
}

// ---------------------------------------------------------------------------
extern "C" void kernel_launch(void* const* d_in, const int* in_sizes, int n_in,
                              void* d_out, int out_size) {
    const int*   indices = (const int*)d_in[0];   // (T, B) int32 (JAX downcast)
    const float* M_prev  = (const float*)d_in[1]; // (E,)   f32
    const float* params  = (const float*)d_in[2]; // (N, 2) f32
    float*       out     = (float*)d_out;         // (T, E) f32

    fused_kernel<<<NTILES, THREADS>>>(indices, params, M_prev, out);
}